// round 11
// baseline (speedup 1.0000x reference)
#include <cuda_runtime.h>
#include <math_constants.h>

#define B_CNT 2
#define S_CNT 1024
#define V_CNT 6890
#define F_CNT 13776
#define NREC  20
#define TILE  128
#define QB    16      // queries per block
#define NQ    4       // queries per thread (register-resident)
#define TPQ   64      // threads cooperating on one query-set (256/4)
#define NTHREADS 256
#define NQTOT (B_CNT * S_CNT)

// SoA face records:
// 0..2 ab | 3..5 ac | 6..8 a | 9 ab·a | 10 ab·b | 11 ab·c | 12 ac·a | 13 ac·b
// 14 ac·c | 15 a·a | 16 ab·ab | 17 ac·ac | 18 ab·ac | 19 pad
__device__ float g_face[NREC][B_CNT * F_CNT];

// Sequential left-assoc, NO fma: subtrahend dots (einsum bfd,bfd->bf) AND pp.
__device__ __forceinline__ float dot3_nofma(float x0,float y0,float z0,
                                            float x1,float y1,float z1) {
    return __fadd_rn(__fadd_rn(__fmul_rn(x0,x1), __fmul_rn(y0,y1)), __fmul_rn(z0,z1));
}
// jnp.sum(x*y,-1) reduces over (B,F,3): 4-lane tree (m0+m2)+(m1+0). NO fma.
__device__ __forceinline__ float dot3_tree(float x0,float y0,float z0,
                                           float x1,float y1,float z1) {
    return __fadd_rn(__fadd_rn(__fmul_rn(x0,x1), __fmul_rn(z0,z1)), __fmul_rn(y0,y1));
}
// big einsum gemm: ascending-k single-accumulator FMA chain.
__device__ __forceinline__ float dot3_fma(float x0,float y0,float z0,
                                          float x1,float y1,float z1) {
    return fmaf(z0, z1, fmaf(y0, y1, __fmul_rn(x0, x1)));
}
__device__ __forceinline__ float safed(float d) { return d == 0.0f ? 1.0f : d; }

__global__ void face_precompute_kernel(const float* __restrict__ smpl_V,
                                       const int*   __restrict__ smpl_F) {
    int idx = blockIdx.x * blockDim.x + threadIdx.x;
    if (idx >= B_CNT * F_CNT) return;
    int b = idx / F_CNT;
    int f = idx - b * F_CNT;
    int i0 = smpl_F[f*3+0], i1 = smpl_F[f*3+1], i2 = smpl_F[f*3+2];
    const float* Vb = smpl_V + (size_t)b * V_CNT * 3;
    float ax = Vb[i0*3+0], ay = Vb[i0*3+1], az = Vb[i0*3+2];
    float bx = Vb[i1*3+0], by = Vb[i1*3+1], bz = Vb[i1*3+2];
    float cx = Vb[i2*3+0], cy = Vb[i2*3+1], cz = Vb[i2*3+2];
    float abx = __fsub_rn(bx,ax), aby = __fsub_rn(by,ay), abz = __fsub_rn(bz,az);
    float acx = __fsub_rn(cx,ax), acy = __fsub_rn(cy,ay), acz = __fsub_rn(cz,az);
    g_face[0][idx]=abx;  g_face[1][idx]=aby;  g_face[2][idx]=abz;
    g_face[3][idx]=acx;  g_face[4][idx]=acy;  g_face[5][idx]=acz;
    g_face[6][idx]=ax;   g_face[7][idx]=ay;   g_face[8][idx]=az;
    // einsum('bfd,bfd->bf') subtrahends: left-assoc nofma
    g_face[9][idx]  = dot3_nofma(abx,aby,abz, ax,ay,az);
    g_face[10][idx] = dot3_nofma(abx,aby,abz, bx,by,bz);
    g_face[11][idx] = dot3_nofma(abx,aby,abz, cx,cy,cz);
    g_face[12][idx] = dot3_nofma(acx,acy,acz, ax,ay,az);
    g_face[13][idx] = dot3_nofma(acx,acy,acz, bx,by,bz);
    g_face[14][idx] = dot3_nofma(acx,acy,acz, cx,cy,cz);
    // jnp.sum(x*y,-1) reduces over (B,F,3): TREE (m0+m2)+m1
    g_face[15][idx] = dot3_tree(ax,ay,az,    ax,ay,az);
    g_face[16][idx] = dot3_tree(abx,aby,abz, abx,aby,abz);
    g_face[17][idx] = dot3_tree(acx,acy,acz, acx,acy,acz);
    g_face[18][idx] = dot3_tree(abx,aby,abz, acx,acy,acz);
    g_face[19][idx] = 0.0f;
}

__global__ __launch_bounds__(NTHREADS)
void smpl_query_kernel(const float* __restrict__ coords,
                       const float* __restrict__ can_V,
                       const int*   __restrict__ smpl_F,
                       float* __restrict__ out) {
    __shared__ float sf[NREC][TILE];
    __shared__ float r_d2[NTHREADS * NQ];
    __shared__ float r_v [NTHREADS * NQ];
    __shared__ float r_w [NTHREADS * NQ];
    __shared__ int   r_f [NTHREADS * NQ];

    int tid   = threadIdx.x;
    int qset  = tid >> 6;     // which group of NQ queries (0..3)
    int flane = tid & 63;     // face lane within query-set
    int qblk  = blockIdx.x * QB;
    int b     = qblk / S_CNT; // all QB queries in block share batch (QB | S)

    float px[NQ], py[NQ], pz[NQ], pp[NQ];
#pragma unroll
    for (int q = 0; q < NQ; q++) {
        int qg = qblk + qset * NQ + q;
        px[q] = coords[qg*3+0];
        py[q] = coords[qg*3+1];
        pz[q] = coords[qg*3+2];
        // HYPOTHESIS r11: pp fused sequentially -> left-assoc nofma
        pp[q] = dot3_nofma(px[q],py[q],pz[q], px[q],py[q],pz[q]);
    }

    float bd2[NQ], bv[NQ], bw[NQ]; int bf[NQ];
#pragma unroll
    for (int q = 0; q < NQ; q++) {
        bd2[q] = CUDART_INF_F; bv[q] = 0.0f; bw[q] = 0.0f; bf[q] = 0x7fffffff;
    }

    const int rbase = b * F_CNT;
    const int ntiles = (F_CNT + TILE - 1) / TILE;
    for (int t = 0; t < ntiles; t++) {
        int f0 = t * TILE;
        int nf = min(TILE, F_CNT - f0);
        for (int i = tid; i < NREC * TILE; i += NTHREADS) {
            int c = i >> 7;        // / TILE
            int j = i & (TILE-1);  // % TILE
            if (j < nf) sf[c][j] = g_face[c][rbase + f0 + j];
        }
        __syncthreads();

        for (int fi = flane; fi < nf; fi += TPQ) {
            float abx = sf[0][fi],  aby = sf[1][fi],  abz = sf[2][fi];
            float acx = sf[3][fi],  acy = sf[4][fi],  acz = sf[5][fi];
            float ax  = sf[6][fi],  ay  = sf[7][fi],  az  = sf[8][fi];
            float ab_a= sf[9][fi],  ab_b= sf[10][fi], ab_c= sf[11][fi];
            float ac_a= sf[12][fi], ac_b= sf[13][fi], ac_c= sf[14][fi];
            float aa  = sf[15][fi], ab2 = sf[16][fi], ac2 = sf[17][fi];
            float abac= sf[18][fi];
            int fg = f0 + fi;
#pragma unroll
            for (int q = 0; q < NQ; q++) {
                // einsum('bfd,bsd->bsf'): asc-k FMA chain (gemm)
                float s  = dot3_fma(abx,aby,abz, px[q],py[q],pz[q]);
                float tt = dot3_fma(acx,acy,acz, px[q],py[q],pz[q]);
                float ap = dot3_fma(ax, ay, az,  px[q],py[q],pz[q]);
                float d1 = __fsub_rn(s,  ab_a), d2 = __fsub_rn(tt, ac_a);
                float d3 = __fsub_rn(s,  ab_b), d4 = __fsub_rn(tt, ac_b);
                float d5 = __fsub_rn(s,  ab_c), d6 = __fsub_rn(tt, ac_c);
                // elementwise: each product rounded; no fma
                float va  = __fsub_rn(__fmul_rn(d3,d6), __fmul_rn(d5,d4));
                float vbb = __fsub_rn(__fmul_rn(d5,d2), __fmul_rn(d1,d6));
                float vcc = __fsub_rn(__fmul_rn(d1,d4), __fmul_rn(d3,d2));
                float denom = __fadd_rn(__fadd_rn(va, vbb), vcc);
                float sden  = safed(denom);
                float v = __fdiv_rn(vbb, sden);
                float w = __fdiv_rn(vcc, sden);
                float d43 = __fsub_rn(d4, d3), d56 = __fsub_rn(d5, d6);
                float tp  = __fdiv_rn(d43, safed(__fadd_rn(d43, d56)));
                if (va  <= 0.0f && d43 >= 0.0f && d56 >= 0.0f) {
                    v = __fsub_rn(1.0f, tp); w = tp;
                }
                if (vbb <= 0.0f && d2 >= 0.0f && d6 <= 0.0f) {
                    v = 0.0f; w = __fdiv_rn(d2, safed(__fsub_rn(d2, d6)));
                }
                if (vcc <= 0.0f && d1 >= 0.0f && d3 <= 0.0f) {
                    v = __fdiv_rn(d1, safed(__fsub_rn(d1, d3))); w = 0.0f;
                }
                if (d6 >= 0.0f && d5 <= d6) { v = 0.0f; w = 1.0f; }
                if (d3 >= 0.0f && d4 <= d3) { v = 1.0f; w = 0.0f; }
                if (d1 <= 0.0f && d2 <= 0.0f) { v = 0.0f; w = 0.0f; }
                // papa = (pp - 2*ap) + aa
                float papa = __fadd_rn(__fsub_rn(pp[q], __fmul_rn(2.0f, ap)), aa);
                // dist2 = ((((papa - 2v*d1) - 2w*d2) + v*v*ab2) + 2v*w*abac) + w*w*ac2
                float t1 = __fmul_rn(__fmul_rn(2.0f, v), d1);
                float e  = __fsub_rn(papa, t1);
                float t2 = __fmul_rn(__fmul_rn(2.0f, w), d2);
                e = __fsub_rn(e, t2);
                float t3 = __fmul_rn(__fmul_rn(v, v), ab2);
                e = __fadd_rn(e, t3);
                float t4 = __fmul_rn(__fmul_rn(__fmul_rn(2.0f, v), w), abac);
                e = __fadd_rn(e, t4);
                float t5 = __fmul_rn(__fmul_rn(w, w), ac2);
                float dist2 = __fadd_rn(e, t5);
                dist2 = fmaxf(dist2, 0.0f);
                if (dist2 < bd2[q]) { bd2[q] = dist2; bf[q] = fg; bv[q] = v; bw[q] = w; }
            }
        }
        __syncthreads();
    }

#pragma unroll
    for (int q = 0; q < NQ; q++) {
        int idx = tid * NQ + q;
        r_d2[idx] = bd2[q]; r_v[idx] = bv[q]; r_w[idx] = bw[q]; r_f[idx] = bf[q];
    }
    __syncthreads();

    if (tid < QB) {
        int qs = tid >> 2, ql = tid & 3;
        float bd = CUDART_INF_F, fv = 0.0f, fw = 0.0f; int fb = 0x7fffffff;
        for (int t2 = 0; t2 < TPQ; t2++) {
            int idx = (qs * TPQ + t2) * NQ + ql;
            float d = r_d2[idx]; int ff = r_f[idx];
            if (d < bd || (d == bd && ff < fb)) { bd = d; fb = ff; fv = r_v[idx]; fw = r_w[idx]; }
        }
        int qg = qblk + tid;
        float qx = coords[qg*3+0], qy = coords[qg*3+1], qz = coords[qg*3+2];
        int ridx = rbase + fb;
        float ax  = g_face[6][ridx], ay  = g_face[7][ridx], az  = g_face[8][ridx];
        float abx = g_face[0][ridx], aby = g_face[1][ridx], abz = g_face[2][ridx];
        float acx = g_face[3][ridx], acy = g_face[4][ridx], acz = g_face[5][ridx];
        // hitpt = (a + v*ab) + w*ac
        float hx = __fadd_rn(__fadd_rn(ax, __fmul_rn(fv,abx)), __fmul_rn(fw,acx));
        float hy = __fadd_rn(__fadd_rn(ay, __fmul_rn(fv,aby)), __fmul_rn(fw,acy));
        float hz = __fadd_rn(__fadd_rn(az, __fmul_rn(fv,abz)), __fmul_rn(fw,acz));
        float dx = __fsub_rn(hx, qx), dy = __fsub_rn(hy, qy), dz = __fsub_rn(hz, qz);
        // jnp.linalg.norm: sum-of-squares reduce -> tree
        float nrm = __fsqrt_rn(dot3_tree(dx,dy,dz, dx,dy,dz));
        float dn  = fmaxf(nrm, 1e-6f);
        float w0  = __fsub_rn(__fsub_rn(1.0f, fv), fw);
        int i0 = smpl_F[fb*3+0], i1 = smpl_F[fb*3+1], i2 = smpl_F[fb*3+2];
        // out_coord: reduce over verts axis (non-minor) -> sequential ascending
        float o0 = __fadd_rn(__fadd_rn(__fmul_rn(can_V[i0*3+0], w0),
                                       __fmul_rn(can_V[i1*3+0], fv)),
                             __fmul_rn(can_V[i2*3+0], fw));
        float o1 = __fadd_rn(__fadd_rn(__fmul_rn(can_V[i0*3+1], w0),
                                       __fmul_rn(can_V[i1*3+1], fv)),
                             __fmul_rn(can_V[i2*3+1], fw));
        float o2 = __fadd_rn(__fadd_rn(__fmul_rn(can_V[i0*3+2], w0),
                                       __fmul_rn(can_V[i1*3+2], fv)),
                             __fmul_rn(can_V[i2*3+2], fw));
        // output layout: out_coord (B,S,3) | sdf (B,S) | normal (B,S,3) | z (B,S,1)
        out[qg*3+0] = o0; out[qg*3+1] = o1; out[qg*3+2] = o2;
        out[NQTOT*3 + qg] = __fsqrt_rn(bd);
        out[NQTOT*4 + qg*3+0] = __fdiv_rn(dx, dn);
        out[NQTOT*4 + qg*3+1] = __fdiv_rn(dy, dn);
        out[NQTOT*4 + qg*3+2] = __fdiv_rn(dz, dn);
        out[NQTOT*7 + qg] = qz;
    }
}

extern "C" void kernel_launch(void* const* d_in, const int* in_sizes, int n_in,
                              void* d_out, int out_size) {
    const float* coords = (const float*)d_in[0];
    const float* smpl_V = (const float*)d_in[1];
    const float* can_V  = (const float*)d_in[2];
    const int*   smpl_F = (const int*)d_in[3];
    float* out = (float*)d_out;

    face_precompute_kernel<<<(B_CNT * F_CNT + 255) / 256, 256>>>(smpl_V, smpl_F);
    smpl_query_kernel<<<NQTOT / QB, NTHREADS>>>(coords, can_V, smpl_F, out);
}

// round 12
// speedup vs baseline: 1.9370x; 1.9370x over previous
#include <cuda_runtime.h>
#include <math_constants.h>

#define B_CNT 2
#define S_CNT 1024
#define V_CNT 6890
#define F_CNT 13776
#define NREC  20
#define TILE  128
#define QB    16      // queries per block
#define NQ    4       // queries per thread (register-resident)
#define TPQ   64      // threads cooperating on one query-set (256/4)
#define NTHREADS 256
#define NQTOT (B_CNT * S_CNT)
#define NS    8                   // face slices
#define FSLICE (F_CNT / NS)       // 1722
#define NQBLK (NQTOT / QB)        // 128 query-blocks

// SoA face records:
// 0..2 ab | 3..5 ac | 6..8 a | 9 ab·a | 10 ab·b | 11 ab·c | 12 ac·a | 13 ac·b
// 14 ac·c | 15 a·a | 16 ab·ab | 17 ac·ac | 18 ab·ac | 19 pad
__device__ float g_face[NREC][B_CNT * F_CNT];
// per-slice partial argmin results
__device__ float g_pd2[NS][NQTOT];
__device__ float g_pv [NS][NQTOT];
__device__ float g_pw [NS][NQTOT];
__device__ int   g_pf [NS][NQTOT];

// Sequential left-assoc, NO fma: subtrahend dots (einsum bfd,bfd->bf) AND pp.
__device__ __forceinline__ float dot3_nofma(float x0,float y0,float z0,
                                            float x1,float y1,float z1) {
    return __fadd_rn(__fadd_rn(__fmul_rn(x0,x1), __fmul_rn(y0,y1)), __fmul_rn(z0,z1));
}
// jnp.sum(x*y,-1) reduces over (B,F,3): 4-lane tree (m0+m2)+(m1+0). NO fma.
__device__ __forceinline__ float dot3_tree(float x0,float y0,float z0,
                                           float x1,float y1,float z1) {
    return __fadd_rn(__fadd_rn(__fmul_rn(x0,x1), __fmul_rn(z0,z1)), __fmul_rn(y0,y1));
}
// big einsum gemm: ascending-k single-accumulator FMA chain.
__device__ __forceinline__ float dot3_fma(float x0,float y0,float z0,
                                          float x1,float y1,float z1) {
    return fmaf(z0, z1, fmaf(y0, y1, __fmul_rn(x0, x1)));
}
__device__ __forceinline__ float safed(float d) { return d == 0.0f ? 1.0f : d; }

__global__ void face_precompute_kernel(const float* __restrict__ smpl_V,
                                       const int*   __restrict__ smpl_F) {
    int idx = blockIdx.x * blockDim.x + threadIdx.x;
    if (idx >= B_CNT * F_CNT) return;
    int b = idx / F_CNT;
    int f = idx - b * F_CNT;
    int i0 = smpl_F[f*3+0], i1 = smpl_F[f*3+1], i2 = smpl_F[f*3+2];
    const float* Vb = smpl_V + (size_t)b * V_CNT * 3;
    float ax = Vb[i0*3+0], ay = Vb[i0*3+1], az = Vb[i0*3+2];
    float bx = Vb[i1*3+0], by = Vb[i1*3+1], bz = Vb[i1*3+2];
    float cx = Vb[i2*3+0], cy = Vb[i2*3+1], cz = Vb[i2*3+2];
    float abx = __fsub_rn(bx,ax), aby = __fsub_rn(by,ay), abz = __fsub_rn(bz,az);
    float acx = __fsub_rn(cx,ax), acy = __fsub_rn(cy,ay), acz = __fsub_rn(cz,az);
    g_face[0][idx]=abx;  g_face[1][idx]=aby;  g_face[2][idx]=abz;
    g_face[3][idx]=acx;  g_face[4][idx]=acy;  g_face[5][idx]=acz;
    g_face[6][idx]=ax;   g_face[7][idx]=ay;   g_face[8][idx]=az;
    // einsum('bfd,bfd->bf') subtrahends: left-assoc nofma
    g_face[9][idx]  = dot3_nofma(abx,aby,abz, ax,ay,az);
    g_face[10][idx] = dot3_nofma(abx,aby,abz, bx,by,bz);
    g_face[11][idx] = dot3_nofma(abx,aby,abz, cx,cy,cz);
    g_face[12][idx] = dot3_nofma(acx,acy,acz, ax,ay,az);
    g_face[13][idx] = dot3_nofma(acx,acy,acz, bx,by,bz);
    g_face[14][idx] = dot3_nofma(acx,acy,acz, cx,cy,cz);
    // jnp.sum(x*y,-1) reduces over (B,F,3): TREE (m0+m2)+m1
    g_face[15][idx] = dot3_tree(ax,ay,az,    ax,ay,az);
    g_face[16][idx] = dot3_tree(abx,aby,abz, abx,aby,abz);
    g_face[17][idx] = dot3_tree(acx,acy,acz, acx,acy,acz);
    g_face[18][idx] = dot3_tree(abx,aby,abz, acx,acy,acz);
    g_face[19][idx] = 0.0f;
}

__global__ __launch_bounds__(NTHREADS, 3)
void smpl_scan_kernel(const float* __restrict__ coords) {
    __shared__ float sf[NREC][TILE];
    __shared__ float r_d2[NTHREADS * NQ];
    __shared__ float r_v [NTHREADS * NQ];
    __shared__ float r_w [NTHREADS * NQ];
    __shared__ int   r_f [NTHREADS * NQ];

    int tid   = threadIdx.x;
    int qset  = tid >> 6;     // which group of NQ queries (0..3)
    int flane = tid & 63;     // face lane within query-set
    int qbid  = blockIdx.x % NQBLK;
    int slice = blockIdx.x / NQBLK;
    int qblk  = qbid * QB;
    int b     = qblk / S_CNT; // all QB queries in block share batch (QB | S)
    int f_lo  = slice * FSLICE;
    int f_hi  = f_lo + FSLICE;

    float px[NQ], py[NQ], pz[NQ], pp[NQ];
#pragma unroll
    for (int q = 0; q < NQ; q++) {
        int qg = qblk + qset * NQ + q;
        px[q] = coords[qg*3+0];
        py[q] = coords[qg*3+1];
        pz[q] = coords[qg*3+2];
        // pp: (B,S,3) reduce -> sequential left-assoc nofma
        pp[q] = dot3_nofma(px[q],py[q],pz[q], px[q],py[q],pz[q]);
    }

    float bd2[NQ], bv[NQ], bw[NQ]; int bf[NQ];
#pragma unroll
    for (int q = 0; q < NQ; q++) {
        bd2[q] = CUDART_INF_F; bv[q] = 0.0f; bw[q] = 0.0f; bf[q] = 0x7fffffff;
    }

    const int rbase = b * F_CNT;
    for (int f0 = f_lo; f0 < f_hi; f0 += TILE) {
        int nf = min(TILE, f_hi - f0);
        for (int i = tid; i < NREC * TILE; i += NTHREADS) {
            int c = i >> 7;        // / TILE
            int j = i & (TILE-1);  // % TILE
            if (j < nf) sf[c][j] = g_face[c][rbase + f0 + j];
        }
        __syncthreads();

        for (int fi = flane; fi < nf; fi += TPQ) {
            float abx = sf[0][fi],  aby = sf[1][fi],  abz = sf[2][fi];
            float acx = sf[3][fi],  acy = sf[4][fi],  acz = sf[5][fi];
            float ax  = sf[6][fi],  ay  = sf[7][fi],  az  = sf[8][fi];
            float ab_a= sf[9][fi],  ab_b= sf[10][fi], ab_c= sf[11][fi];
            float ac_a= sf[12][fi], ac_b= sf[13][fi], ac_c= sf[14][fi];
            float aa  = sf[15][fi], ab2 = sf[16][fi], ac2 = sf[17][fi];
            float abac= sf[18][fi];
            int fg = f0 + fi;
#pragma unroll
            for (int q = 0; q < NQ; q++) {
                // einsum('bfd,bsd->bsf'): asc-k FMA chain (gemm)
                float s  = dot3_fma(abx,aby,abz, px[q],py[q],pz[q]);
                float tt = dot3_fma(acx,acy,acz, px[q],py[q],pz[q]);
                float ap = dot3_fma(ax, ay, az,  px[q],py[q],pz[q]);
                float d1 = __fsub_rn(s,  ab_a), d2 = __fsub_rn(tt, ac_a);
                float d3 = __fsub_rn(s,  ab_b), d4 = __fsub_rn(tt, ac_b);
                float d5 = __fsub_rn(s,  ab_c), d6 = __fsub_rn(tt, ac_c);
                // elementwise: each product rounded; no fma
                float va  = __fsub_rn(__fmul_rn(d3,d6), __fmul_rn(d5,d4));
                float vbb = __fsub_rn(__fmul_rn(d5,d2), __fmul_rn(d1,d6));
                float vcc = __fsub_rn(__fmul_rn(d1,d4), __fmul_rn(d3,d2));
                float denom = __fadd_rn(__fadd_rn(va, vbb), vcc);
                float sden  = safed(denom);
                float v = __fdiv_rn(vbb, sden);
                float w = __fdiv_rn(vcc, sden);
                float d43 = __fsub_rn(d4, d3), d56 = __fsub_rn(d5, d6);
                float tp  = __fdiv_rn(d43, safed(__fadd_rn(d43, d56)));
                if (va  <= 0.0f && d43 >= 0.0f && d56 >= 0.0f) {
                    v = __fsub_rn(1.0f, tp); w = tp;
                }
                if (vbb <= 0.0f && d2 >= 0.0f && d6 <= 0.0f) {
                    v = 0.0f; w = __fdiv_rn(d2, safed(__fsub_rn(d2, d6)));
                }
                if (vcc <= 0.0f && d1 >= 0.0f && d3 <= 0.0f) {
                    v = __fdiv_rn(d1, safed(__fsub_rn(d1, d3))); w = 0.0f;
                }
                if (d6 >= 0.0f && d5 <= d6) { v = 0.0f; w = 1.0f; }
                if (d3 >= 0.0f && d4 <= d3) { v = 1.0f; w = 0.0f; }
                if (d1 <= 0.0f && d2 <= 0.0f) { v = 0.0f; w = 0.0f; }
                // papa = (pp - 2*ap) + aa
                float papa = __fadd_rn(__fsub_rn(pp[q], __fmul_rn(2.0f, ap)), aa);
                // dist2 = ((((papa - 2v*d1) - 2w*d2) + v*v*ab2) + 2v*w*abac) + w*w*ac2
                float t1 = __fmul_rn(__fmul_rn(2.0f, v), d1);
                float e  = __fsub_rn(papa, t1);
                float t2 = __fmul_rn(__fmul_rn(2.0f, w), d2);
                e = __fsub_rn(e, t2);
                float t3 = __fmul_rn(__fmul_rn(v, v), ab2);
                e = __fadd_rn(e, t3);
                float t4 = __fmul_rn(__fmul_rn(__fmul_rn(2.0f, v), w), abac);
                e = __fadd_rn(e, t4);
                float t5 = __fmul_rn(__fmul_rn(w, w), ac2);
                float dist2 = __fadd_rn(e, t5);
                dist2 = fmaxf(dist2, 0.0f);
                if (dist2 < bd2[q]) { bd2[q] = dist2; bf[q] = fg; bv[q] = v; bw[q] = w; }
            }
        }
        __syncthreads();
    }

#pragma unroll
    for (int q = 0; q < NQ; q++) {
        int idx = tid * NQ + q;
        r_d2[idx] = bd2[q]; r_v[idx] = bv[q]; r_w[idx] = bw[q]; r_f[idx] = bf[q];
    }
    __syncthreads();

    if (tid < QB) {
        int qs = tid >> 2, ql = tid & 3;
        float bd = CUDART_INF_F, fv = 0.0f, fw = 0.0f; int fb = 0x7fffffff;
        for (int t2 = 0; t2 < TPQ; t2++) {
            int idx = (qs * TPQ + t2) * NQ + ql;
            float d = r_d2[idx]; int ff = r_f[idx];
            if (d < bd || (d == bd && ff < fb)) { bd = d; fb = ff; fv = r_v[idx]; fw = r_w[idx]; }
        }
        int qg = qblk + tid;
        g_pd2[slice][qg] = bd;
        g_pv [slice][qg] = fv;
        g_pw [slice][qg] = fw;
        g_pf [slice][qg] = fb;
    }
}

__global__ void smpl_finalize_kernel(const float* __restrict__ coords,
                                     const float* __restrict__ can_V,
                                     const int*   __restrict__ smpl_F,
                                     float* __restrict__ out) {
    int qg = blockIdx.x * blockDim.x + threadIdx.x;
    if (qg >= NQTOT) return;
    int b = qg / S_CNT;
    const int rbase = b * F_CNT;

    float bd = CUDART_INF_F, fv = 0.0f, fw = 0.0f; int fb = 0x7fffffff;
    for (int s = 0; s < NS; s++) {
        float d = g_pd2[s][qg]; int ff = g_pf[s][qg];
        if (d < bd || (d == bd && ff < fb)) {
            bd = d; fb = ff; fv = g_pv[s][qg]; fw = g_pw[s][qg];
        }
    }

    float qx = coords[qg*3+0], qy = coords[qg*3+1], qz = coords[qg*3+2];
    int ridx = rbase + fb;
    float ax  = g_face[6][ridx], ay  = g_face[7][ridx], az  = g_face[8][ridx];
    float abx = g_face[0][ridx], aby = g_face[1][ridx], abz = g_face[2][ridx];
    float acx = g_face[3][ridx], acy = g_face[4][ridx], acz = g_face[5][ridx];
    // hitpt = (a + v*ab) + w*ac
    float hx = __fadd_rn(__fadd_rn(ax, __fmul_rn(fv,abx)), __fmul_rn(fw,acx));
    float hy = __fadd_rn(__fadd_rn(ay, __fmul_rn(fv,aby)), __fmul_rn(fw,acy));
    float hz = __fadd_rn(__fadd_rn(az, __fmul_rn(fv,abz)), __fmul_rn(fw,acz));
    float dx = __fsub_rn(hx, qx), dy = __fsub_rn(hy, qy), dz = __fsub_rn(hz, qz);
    // jnp.linalg.norm: sum-of-squares reduce -> tree
    float nrm = __fsqrt_rn(dot3_tree(dx,dy,dz, dx,dy,dz));
    float dn  = fmaxf(nrm, 1e-6f);
    float w0  = __fsub_rn(__fsub_rn(1.0f, fv), fw);
    int i0 = smpl_F[fb*3+0], i1 = smpl_F[fb*3+1], i2 = smpl_F[fb*3+2];
    // out_coord: reduce over verts axis (non-minor) -> sequential ascending
    float o0 = __fadd_rn(__fadd_rn(__fmul_rn(can_V[i0*3+0], w0),
                                   __fmul_rn(can_V[i1*3+0], fv)),
                         __fmul_rn(can_V[i2*3+0], fw));
    float o1 = __fadd_rn(__fadd_rn(__fmul_rn(can_V[i0*3+1], w0),
                                   __fmul_rn(can_V[i1*3+1], fv)),
                         __fmul_rn(can_V[i2*3+1], fw));
    float o2 = __fadd_rn(__fadd_rn(__fmul_rn(can_V[i0*3+2], w0),
                                   __fmul_rn(can_V[i1*3+2], fv)),
                         __fmul_rn(can_V[i2*3+2], fw));
    // output layout: out_coord (B,S,3) | sdf (B,S) | normal (B,S,3) | z (B,S,1)
    out[qg*3+0] = o0; out[qg*3+1] = o1; out[qg*3+2] = o2;
    out[NQTOT*3 + qg] = __fsqrt_rn(bd);
    out[NQTOT*4 + qg*3+0] = __fdiv_rn(dx, dn);
    out[NQTOT*4 + qg*3+1] = __fdiv_rn(dy, dn);
    out[NQTOT*4 + qg*3+2] = __fdiv_rn(dz, dn);
    out[NQTOT*7 + qg] = qz;
}

extern "C" void kernel_launch(void* const* d_in, const int* in_sizes, int n_in,
                              void* d_out, int out_size) {
    const float* coords = (const float*)d_in[0];
    const float* smpl_V = (const float*)d_in[1];
    const float* can_V  = (const float*)d_in[2];
    const int*   smpl_F = (const int*)d_in[3];
    float* out = (float*)d_out;

    face_precompute_kernel<<<(B_CNT * F_CNT + 255) / 256, 256>>>(smpl_V, smpl_F);
    smpl_scan_kernel<<<NS * NQBLK, NTHREADS>>>(coords);
    smpl_finalize_kernel<<<(NQTOT + 255) / 256, 256>>>(coords, can_V, smpl_F, out);
}

// round 13
// speedup vs baseline: 2.0297x; 1.0478x over previous
#include <cuda_runtime.h>
#include <math_constants.h>

#define B_CNT 2
#define S_CNT 1024
#define V_CNT 6890
#define F_CNT 13776
#define NREC  20
#define TILE  128
#define QB    16      // queries per block
#define NQ    4       // queries per thread (register-resident)
#define TPQ   64      // threads cooperating on one query-set (256/4)
#define NTHREADS 256
#define NQTOT (B_CNT * S_CNT)
#define NS    10                  // face slices
#define FSLICE ((F_CNT + NS - 1) / NS)   // 1378
#define NQBLK (NQTOT / QB)        // 128 query-blocks

// SoA face records:
// 0..2 ab | 3..5 ac | 6..8 a | 9 ab·a | 10 ab·b | 11 ab·c | 12 ac·a | 13 ac·b
// 14 ac·c | 15 a·a | 16 ab·ab | 17 ac·ac | 18 ab·ac | 19 pad
__device__ float g_face[NREC][B_CNT * F_CNT];
// per-slice partial argmin results
__device__ float g_pd2[NS][NQTOT];
__device__ float g_pv [NS][NQTOT];
__device__ float g_pw [NS][NQTOT];
__device__ int   g_pf [NS][NQTOT];

// Sequential left-assoc, NO fma: subtrahend dots (einsum bfd,bfd->bf) AND pp.
__device__ __forceinline__ float dot3_nofma(float x0,float y0,float z0,
                                            float x1,float y1,float z1) {
    return __fadd_rn(__fadd_rn(__fmul_rn(x0,x1), __fmul_rn(y0,y1)), __fmul_rn(z0,z1));
}
// jnp.sum(x*y,-1) reduces over (B,F,3): 4-lane tree (m0+m2)+(m1+0). NO fma.
__device__ __forceinline__ float dot3_tree(float x0,float y0,float z0,
                                           float x1,float y1,float z1) {
    return __fadd_rn(__fadd_rn(__fmul_rn(x0,x1), __fmul_rn(z0,z1)), __fmul_rn(y0,y1));
}
// big einsum gemm: ascending-k single-accumulator FMA chain.
__device__ __forceinline__ float dot3_fma(float x0,float y0,float z0,
                                          float x1,float y1,float z1) {
    return fmaf(z0, z1, fmaf(y0, y1, __fmul_rn(x0, x1)));
}
__device__ __forceinline__ float safed(float d) { return d == 0.0f ? 1.0f : d; }

__global__ void face_precompute_kernel(const float* __restrict__ smpl_V,
                                       const int*   __restrict__ smpl_F) {
    int idx = blockIdx.x * blockDim.x + threadIdx.x;
    if (idx >= B_CNT * F_CNT) return;
    int b = idx / F_CNT;
    int f = idx - b * F_CNT;
    int i0 = smpl_F[f*3+0], i1 = smpl_F[f*3+1], i2 = smpl_F[f*3+2];
    const float* Vb = smpl_V + (size_t)b * V_CNT * 3;
    float ax = Vb[i0*3+0], ay = Vb[i0*3+1], az = Vb[i0*3+2];
    float bx = Vb[i1*3+0], by = Vb[i1*3+1], bz = Vb[i1*3+2];
    float cx = Vb[i2*3+0], cy = Vb[i2*3+1], cz = Vb[i2*3+2];
    float abx = __fsub_rn(bx,ax), aby = __fsub_rn(by,ay), abz = __fsub_rn(bz,az);
    float acx = __fsub_rn(cx,ax), acy = __fsub_rn(cy,ay), acz = __fsub_rn(cz,az);
    g_face[0][idx]=abx;  g_face[1][idx]=aby;  g_face[2][idx]=abz;
    g_face[3][idx]=acx;  g_face[4][idx]=acy;  g_face[5][idx]=acz;
    g_face[6][idx]=ax;   g_face[7][idx]=ay;   g_face[8][idx]=az;
    // einsum('bfd,bfd->bf') subtrahends: left-assoc nofma
    g_face[9][idx]  = dot3_nofma(abx,aby,abz, ax,ay,az);
    g_face[10][idx] = dot3_nofma(abx,aby,abz, bx,by,bz);
    g_face[11][idx] = dot3_nofma(abx,aby,abz, cx,cy,cz);
    g_face[12][idx] = dot3_nofma(acx,acy,acz, ax,ay,az);
    g_face[13][idx] = dot3_nofma(acx,acy,acz, bx,by,bz);
    g_face[14][idx] = dot3_nofma(acx,acy,acz, cx,cy,cz);
    // jnp.sum(x*y,-1) reduces over (B,F,3): TREE (m0+m2)+m1
    g_face[15][idx] = dot3_tree(ax,ay,az,    ax,ay,az);
    g_face[16][idx] = dot3_tree(abx,aby,abz, abx,aby,abz);
    g_face[17][idx] = dot3_tree(acx,acy,acz, acx,acy,acz);
    g_face[18][idx] = dot3_tree(abx,aby,abz, acx,acy,acz);
    g_face[19][idx] = 0.0f;
}

__global__ __launch_bounds__(NTHREADS, 3)
void smpl_scan_kernel(const float* __restrict__ coords) {
    __shared__ float sf[NREC][TILE];
    __shared__ float r_d2[NTHREADS * NQ];
    __shared__ float r_v [NTHREADS * NQ];
    __shared__ float r_w [NTHREADS * NQ];
    __shared__ int   r_f [NTHREADS * NQ];

    int tid   = threadIdx.x;
    int qset  = tid >> 6;     // which group of NQ queries (0..3)
    int flane = tid & 63;     // face lane within query-set
    int qbid  = blockIdx.x % NQBLK;
    int slice = blockIdx.x / NQBLK;
    int qblk  = qbid * QB;
    int b     = qblk / S_CNT; // all QB queries in block share batch (QB | S)
    int f_lo  = slice * FSLICE;
    int f_hi  = min(f_lo + FSLICE, F_CNT);

    float px[NQ], py[NQ], pz[NQ], pp[NQ];
#pragma unroll
    for (int q = 0; q < NQ; q++) {
        int qg = qblk + qset * NQ + q;
        px[q] = coords[qg*3+0];
        py[q] = coords[qg*3+1];
        pz[q] = coords[qg*3+2];
        // pp: (B,S,3) reduce -> sequential left-assoc nofma
        pp[q] = dot3_nofma(px[q],py[q],pz[q], px[q],py[q],pz[q]);
    }

    float bd2[NQ], bv[NQ], bw[NQ]; int bf[NQ];
#pragma unroll
    for (int q = 0; q < NQ; q++) {
        bd2[q] = CUDART_INF_F; bv[q] = 0.0f; bw[q] = 0.0f; bf[q] = 0x7fffffff;
    }

    const int rbase = b * F_CNT;
    for (int f0 = f_lo; f0 < f_hi; f0 += TILE) {
        int nf = min(TILE, f_hi - f0);
        for (int i = tid; i < NREC * TILE; i += NTHREADS) {
            int c = i >> 7;        // / TILE
            int j = i & (TILE-1);  // % TILE
            if (j < nf) sf[c][j] = g_face[c][rbase + f0 + j];
        }
        __syncthreads();

        for (int fi = flane; fi < nf; fi += TPQ) {
            float abx = sf[0][fi],  aby = sf[1][fi],  abz = sf[2][fi];
            float acx = sf[3][fi],  acy = sf[4][fi],  acz = sf[5][fi];
            float ax  = sf[6][fi],  ay  = sf[7][fi],  az  = sf[8][fi];
            float ab_a= sf[9][fi],  ab_b= sf[10][fi], ab_c= sf[11][fi];
            float ac_a= sf[12][fi], ac_b= sf[13][fi], ac_c= sf[14][fi];
            float aa  = sf[15][fi], ab2 = sf[16][fi], ac2 = sf[17][fi];
            float abac= sf[18][fi];
            int fg = f0 + fi;
#pragma unroll
            for (int q = 0; q < NQ; q++) {
                // einsum('bfd,bsd->bsf'): asc-k FMA chain (gemm)
                float s  = dot3_fma(abx,aby,abz, px[q],py[q],pz[q]);
                float tt = dot3_fma(acx,acy,acz, px[q],py[q],pz[q]);
                float ap = dot3_fma(ax, ay, az,  px[q],py[q],pz[q]);
                float d1 = __fsub_rn(s,  ab_a), d2 = __fsub_rn(tt, ac_a);
                float d3 = __fsub_rn(s,  ab_b), d4 = __fsub_rn(tt, ac_b);
                float d5 = __fsub_rn(s,  ab_c), d6 = __fsub_rn(tt, ac_c);
                // elementwise: each product rounded; no fma
                float va  = __fsub_rn(__fmul_rn(d3,d6), __fmul_rn(d5,d4));
                float vbb = __fsub_rn(__fmul_rn(d5,d2), __fmul_rn(d1,d6));
                float vcc = __fsub_rn(__fmul_rn(d1,d4), __fmul_rn(d3,d2));
                float denom = __fadd_rn(__fadd_rn(va, vbb), vcc);
                float sden  = safed(denom);
                float d43 = __fsub_rn(d4, d3), d56 = __fsub_rn(d5, d6);
                // where-chain region (last-true-wins = highest index)
                int reg = 0;  // interior
                if (va  <= 0.0f && d43 >= 0.0f && d56 >= 0.0f) reg = 1;
                if (vbb <= 0.0f && d2  >= 0.0f && d6  <= 0.0f) reg = 2;
                if (vcc <= 0.0f && d1  >= 0.0f && d3  <= 0.0f) reg = 3;
                if (d6 >= 0.0f && d5 <= d6)                    reg = 4;
                if (d3 >= 0.0f && d4 <= d3)                    reg = 5;
                if (d1 <= 0.0f && d2 <= 0.0f)                  reg = 6;
                // only 2 actual divides; bit-exact operands per selected region
                float numA = vbb, denA = sden;     // interior v
                float numB = vcc, denB = sden;     // interior w
                if (reg == 1) { numA = d43; denA = safed(__fadd_rn(d43, d56)); }
                if (reg == 3) { numA = d1;  denA = safed(__fsub_rn(d1, d3)); }
                if (reg == 2) { numB = d2;  denB = safed(__fsub_rn(d2, d6)); }
                float rA = __fdiv_rn(numA, denA);
                float rB = __fdiv_rn(numB, denB);
                float v = rA, w = rB;              // interior
                if (reg == 1) { v = __fsub_rn(1.0f, rA); w = rA; }
                if (reg == 2) { v = 0.0f; w = rB; }
                if (reg == 3) { v = rA;   w = 0.0f; }
                if (reg == 4) { v = 0.0f; w = 1.0f; }
                if (reg == 5) { v = 1.0f; w = 0.0f; }
                if (reg == 6) { v = 0.0f; w = 0.0f; }
                // papa = (pp - 2*ap) + aa
                float papa = __fadd_rn(__fsub_rn(pp[q], __fmul_rn(2.0f, ap)), aa);
                // dist2 = ((((papa - 2v*d1) - 2w*d2) + v*v*ab2) + 2v*w*abac) + w*w*ac2
                float t1 = __fmul_rn(__fmul_rn(2.0f, v), d1);
                float e  = __fsub_rn(papa, t1);
                float t2 = __fmul_rn(__fmul_rn(2.0f, w), d2);
                e = __fsub_rn(e, t2);
                float t3 = __fmul_rn(__fmul_rn(v, v), ab2);
                e = __fadd_rn(e, t3);
                float t4 = __fmul_rn(__fmul_rn(__fmul_rn(2.0f, v), w), abac);
                e = __fadd_rn(e, t4);
                float t5 = __fmul_rn(__fmul_rn(w, w), ac2);
                float dist2 = __fadd_rn(e, t5);
                dist2 = fmaxf(dist2, 0.0f);
                if (dist2 < bd2[q]) { bd2[q] = dist2; bf[q] = fg; bv[q] = v; bw[q] = w; }
            }
        }
        __syncthreads();
    }

#pragma unroll
    for (int q = 0; q < NQ; q++) {
        int idx = tid * NQ + q;
        r_d2[idx] = bd2[q]; r_v[idx] = bv[q]; r_w[idx] = bw[q]; r_f[idx] = bf[q];
    }
    __syncthreads();

    if (tid < QB) {
        int qs = tid >> 2, ql = tid & 3;
        float bd = CUDART_INF_F, fv = 0.0f, fw = 0.0f; int fb = 0x7fffffff;
        for (int t2 = 0; t2 < TPQ; t2++) {
            int idx = (qs * TPQ + t2) * NQ + ql;
            float d = r_d2[idx]; int ff = r_f[idx];
            if (d < bd || (d == bd && ff < fb)) { bd = d; fb = ff; fv = r_v[idx]; fw = r_w[idx]; }
        }
        int qg = qblk + tid;
        g_pd2[slice][qg] = bd;
        g_pv [slice][qg] = fv;
        g_pw [slice][qg] = fw;
        g_pf [slice][qg] = fb;
    }
}

__global__ void smpl_finalize_kernel(const float* __restrict__ coords,
                                     const float* __restrict__ can_V,
                                     const int*   __restrict__ smpl_F,
                                     float* __restrict__ out) {
    int qg = blockIdx.x * blockDim.x + threadIdx.x;
    if (qg >= NQTOT) return;
    int b = qg / S_CNT;
    const int rbase = b * F_CNT;

    float bd = CUDART_INF_F, fv = 0.0f, fw = 0.0f; int fb = 0x7fffffff;
    for (int s = 0; s < NS; s++) {
        float d = g_pd2[s][qg]; int ff = g_pf[s][qg];
        if (d < bd || (d == bd && ff < fb)) {
            bd = d; fb = ff; fv = g_pv[s][qg]; fw = g_pw[s][qg];
        }
    }

    float qx = coords[qg*3+0], qy = coords[qg*3+1], qz = coords[qg*3+2];
    int ridx = rbase + fb;
    float ax  = g_face[6][ridx], ay  = g_face[7][ridx], az  = g_face[8][ridx];
    float abx = g_face[0][ridx], aby = g_face[1][ridx], abz = g_face[2][ridx];
    float acx = g_face[3][ridx], acy = g_face[4][ridx], acz = g_face[5][ridx];
    // hitpt = (a + v*ab) + w*ac
    float hx = __fadd_rn(__fadd_rn(ax, __fmul_rn(fv,abx)), __fmul_rn(fw,acx));
    float hy = __fadd_rn(__fadd_rn(ay, __fmul_rn(fv,aby)), __fmul_rn(fw,acy));
    float hz = __fadd_rn(__fadd_rn(az, __fmul_rn(fv,abz)), __fmul_rn(fw,acz));
    float dx = __fsub_rn(hx, qx), dy = __fsub_rn(hy, qy), dz = __fsub_rn(hz, qz);
    // jnp.linalg.norm: sum-of-squares reduce -> tree
    float nrm = __fsqrt_rn(dot3_tree(dx,dy,dz, dx,dy,dz));
    float dn  = fmaxf(nrm, 1e-6f);
    float w0  = __fsub_rn(__fsub_rn(1.0f, fv), fw);
    int i0 = smpl_F[fb*3+0], i1 = smpl_F[fb*3+1], i2 = smpl_F[fb*3+2];
    // out_coord: reduce over verts axis (non-minor) -> sequential ascending
    float o0 = __fadd_rn(__fadd_rn(__fmul_rn(can_V[i0*3+0], w0),
                                   __fmul_rn(can_V[i1*3+0], fv)),
                         __fmul_rn(can_V[i2*3+0], fw));
    float o1 = __fadd_rn(__fadd_rn(__fmul_rn(can_V[i0*3+1], w0),
                                   __fmul_rn(can_V[i1*3+1], fv)),
                         __fmul_rn(can_V[i2*3+1], fw));
    float o2 = __fadd_rn(__fadd_rn(__fmul_rn(can_V[i0*3+2], w0),
                                   __fmul_rn(can_V[i1*3+2], fv)),
                         __fmul_rn(can_V[i2*3+2], fw));
    // output layout: out_coord (B,S,3) | sdf (B,S) | normal (B,S,3) | z (B,S,1)
    out[qg*3+0] = o0; out[qg*3+1] = o1; out[qg*3+2] = o2;
    out[NQTOT*3 + qg] = __fsqrt_rn(bd);
    out[NQTOT*4 + qg*3+0] = __fdiv_rn(dx, dn);
    out[NQTOT*4 + qg*3+1] = __fdiv_rn(dy, dn);
    out[NQTOT*4 + qg*3+2] = __fdiv_rn(dz, dn);
    out[NQTOT*7 + qg] = qz;
}

extern "C" void kernel_launch(void* const* d_in, const int* in_sizes, int n_in,
                              void* d_out, int out_size) {
    const float* coords = (const float*)d_in[0];
    const float* smpl_V = (const float*)d_in[1];
    const float* can_V  = (const float*)d_in[2];
    const int*   smpl_F = (const int*)d_in[3];
    float* out = (float*)d_out;

    face_precompute_kernel<<<(B_CNT * F_CNT + 255) / 256, 256>>>(smpl_V, smpl_F);
    smpl_scan_kernel<<<NS * NQBLK, NTHREADS>>>(coords);
    smpl_finalize_kernel<<<(NQTOT + 255) / 256, 256>>>(coords, can_V, smpl_F, out);
}

// round 15
// speedup vs baseline: 2.1833x; 1.0757x over previous
#include <cuda_runtime.h>
#include <math_constants.h>

#define B_CNT 2
#define S_CNT 1024
#define V_CNT 6890
#define F_CNT 13776
#define NREC  20
#define TILE  128
#define QB    16      // queries per block
#define NQ    4       // queries per thread (register-resident)
#define TPQ   64      // threads cooperating on one query-set (256/4)
#define NTHREADS 256
#define NQTOT (B_CNT * S_CNT)
#define NS    18                  // face slices
#define FSLICE ((F_CNT + NS - 1) / NS)   // 766
#define NQBLK (NQTOT / QB)        // 128 query-blocks

// SoA face records:
// 0..2 ab | 3..5 ac | 6..8 a | 9 ab·a | 10 ab·b | 11 ab·c | 12 ac·a | 13 ac·b
// 14 ac·c | 15 a·a | 16 ab·ab | 17 ac·ac | 18 ab·ac | 19 pad
__device__ float g_face[NREC][B_CNT * F_CNT];
// per-slice partial argmin results (d2 + fid only; v,w recomputed for winner)
__device__ float g_pd2[NS][NQTOT];
__device__ int   g_pf [NS][NQTOT];

// Sequential left-assoc, NO fma: subtrahend dots (einsum bfd,bfd->bf) AND pp.
__device__ __forceinline__ float dot3_nofma(float x0,float y0,float z0,
                                            float x1,float y1,float z1) {
    return __fadd_rn(__fadd_rn(__fmul_rn(x0,x1), __fmul_rn(y0,y1)), __fmul_rn(z0,z1));
}
// jnp.sum(x*y,-1) reduces over (B,F,3): 4-lane tree (m0+m2)+(m1+0). NO fma.
__device__ __forceinline__ float dot3_tree(float x0,float y0,float z0,
                                           float x1,float y1,float z1) {
    return __fadd_rn(__fadd_rn(__fmul_rn(x0,x1), __fmul_rn(z0,z1)), __fmul_rn(y0,y1));
}
// big einsum gemm: ascending-k single-accumulator FMA chain.
__device__ __forceinline__ float dot3_fma(float x0,float y0,float z0,
                                          float x1,float y1,float z1) {
    return fmaf(z0, z1, fmaf(y0, y1, __fmul_rn(x0, x1)));
}
__device__ __forceinline__ float safed(float d) { return d == 0.0f ? 1.0f : d; }

// Bit-exact v,w for one (query, face) pair — shared by scan (implicitly, via
// identical code) and finalize (recompute for winner).
__device__ __forceinline__ void region_vw(
    float s, float tt,
    float ab_a, float ab_b, float ab_c, float ac_a, float ac_b, float ac_c,
    float& v_out, float& w_out)
{
    float d1 = __fsub_rn(s,  ab_a), d2 = __fsub_rn(tt, ac_a);
    float d3 = __fsub_rn(s,  ab_b), d4 = __fsub_rn(tt, ac_b);
    float d5 = __fsub_rn(s,  ab_c), d6 = __fsub_rn(tt, ac_c);
    float va  = __fsub_rn(__fmul_rn(d3,d6), __fmul_rn(d5,d4));
    float vbb = __fsub_rn(__fmul_rn(d5,d2), __fmul_rn(d1,d6));
    float vcc = __fsub_rn(__fmul_rn(d1,d4), __fmul_rn(d3,d2));
    float denom = __fadd_rn(__fadd_rn(va, vbb), vcc);
    float sden  = safed(denom);
    float d43 = __fsub_rn(d4, d3), d56 = __fsub_rn(d5, d6);
    int reg = 0;
    if (va  <= 0.0f && d43 >= 0.0f && d56 >= 0.0f) reg = 1;
    if (vbb <= 0.0f && d2  >= 0.0f && d6  <= 0.0f) reg = 2;
    if (vcc <= 0.0f && d1  >= 0.0f && d3  <= 0.0f) reg = 3;
    if (d6 >= 0.0f && d5 <= d6)                    reg = 4;
    if (d3 >= 0.0f && d4 <= d3)                    reg = 5;
    if (d1 <= 0.0f && d2 <= 0.0f)                  reg = 6;
    float numA = vbb, denA = sden;     // interior v
    float numB = vcc, denB = sden;     // interior w
    if (reg == 1) { numA = d43; denA = safed(__fadd_rn(d43, d56)); }
    if (reg == 3) { numA = d1;  denA = safed(__fsub_rn(d1, d3)); }
    if (reg == 2) { numB = d2;  denB = safed(__fsub_rn(d2, d6)); }
    float rA = __fdiv_rn(numA, denA);
    float rB = __fdiv_rn(numB, denB);
    float v = rA, w = rB;
    if (reg == 1) { v = __fsub_rn(1.0f, rA); w = rA; }
    if (reg == 2) { v = 0.0f; w = rB; }
    if (reg == 3) { v = rA;   w = 0.0f; }
    if (reg == 4) { v = 0.0f; w = 1.0f; }
    if (reg == 5) { v = 1.0f; w = 0.0f; }
    if (reg == 6) { v = 0.0f; w = 0.0f; }
    v_out = v; w_out = w;
}

__global__ void face_precompute_kernel(const float* __restrict__ smpl_V,
                                       const int*   __restrict__ smpl_F) {
    int idx = blockIdx.x * blockDim.x + threadIdx.x;
    if (idx >= B_CNT * F_CNT) return;
    int b = idx / F_CNT;
    int f = idx - b * F_CNT;
    int i0 = smpl_F[f*3+0], i1 = smpl_F[f*3+1], i2 = smpl_F[f*3+2];
    const float* Vb = smpl_V + (size_t)b * V_CNT * 3;
    float ax = Vb[i0*3+0], ay = Vb[i0*3+1], az = Vb[i0*3+2];
    float bx = Vb[i1*3+0], by = Vb[i1*3+1], bz = Vb[i1*3+2];
    float cx = Vb[i2*3+0], cy = Vb[i2*3+1], cz = Vb[i2*3+2];
    float abx = __fsub_rn(bx,ax), aby = __fsub_rn(by,ay), abz = __fsub_rn(bz,az);
    float acx = __fsub_rn(cx,ax), acy = __fsub_rn(cy,ay), acz = __fsub_rn(cz,az);
    g_face[0][idx]=abx;  g_face[1][idx]=aby;  g_face[2][idx]=abz;
    g_face[3][idx]=acx;  g_face[4][idx]=acy;  g_face[5][idx]=acz;
    g_face[6][idx]=ax;   g_face[7][idx]=ay;   g_face[8][idx]=az;
    // einsum('bfd,bfd->bf') subtrahends: left-assoc nofma
    g_face[9][idx]  = dot3_nofma(abx,aby,abz, ax,ay,az);
    g_face[10][idx] = dot3_nofma(abx,aby,abz, bx,by,bz);
    g_face[11][idx] = dot3_nofma(abx,aby,abz, cx,cy,cz);
    g_face[12][idx] = dot3_nofma(acx,acy,acz, ax,ay,az);
    g_face[13][idx] = dot3_nofma(acx,acy,acz, bx,by,bz);
    g_face[14][idx] = dot3_nofma(acx,acy,acz, cx,cy,cz);
    // jnp.sum(x*y,-1) reduces over (B,F,3): TREE (m0+m2)+m1
    g_face[15][idx] = dot3_tree(ax,ay,az,    ax,ay,az);
    g_face[16][idx] = dot3_tree(abx,aby,abz, abx,aby,abz);
    g_face[17][idx] = dot3_tree(acx,acy,acz, acx,acy,acz);
    g_face[18][idx] = dot3_tree(abx,aby,abz, acx,acy,acz);
    g_face[19][idx] = 0.0f;
}

__global__ __launch_bounds__(NTHREADS, 3)
void smpl_scan_kernel(const float* __restrict__ coords) {
    __shared__ float sf[NREC][TILE];
    __shared__ float r_d2[NTHREADS * NQ];
    __shared__ int   r_f [NTHREADS * NQ];

    int tid   = threadIdx.x;
    int qset  = tid >> 6;     // which group of NQ queries (0..3)
    int flane = tid & 63;     // face lane within query-set
    int qbid  = blockIdx.x % NQBLK;
    int slice = blockIdx.x / NQBLK;
    int qblk  = qbid * QB;
    int b     = qblk / S_CNT; // all QB queries in block share batch (QB | S)
    int f_lo  = slice * FSLICE;
    int f_hi  = min(f_lo + FSLICE, F_CNT);

    float px[NQ], py[NQ], pz[NQ], pp[NQ];
#pragma unroll
    for (int q = 0; q < NQ; q++) {
        int qg = qblk + qset * NQ + q;
        px[q] = coords[qg*3+0];
        py[q] = coords[qg*3+1];
        pz[q] = coords[qg*3+2];
        // pp: (B,S,3) reduce -> sequential left-assoc nofma
        pp[q] = dot3_nofma(px[q],py[q],pz[q], px[q],py[q],pz[q]);
    }

    float bd2[NQ]; int bf[NQ];
#pragma unroll
    for (int q = 0; q < NQ; q++) { bd2[q] = CUDART_INF_F; bf[q] = 0x7fffffff; }

    const int rbase = b * F_CNT;
    for (int f0 = f_lo; f0 < f_hi; f0 += TILE) {
        int nf = min(TILE, f_hi - f0);
        for (int i = tid; i < NREC * TILE; i += NTHREADS) {
            int c = i >> 7;        // / TILE
            int j = i & (TILE-1);  // % TILE
            if (j < nf) sf[c][j] = g_face[c][rbase + f0 + j];
        }
        __syncthreads();

        for (int fi = flane; fi < nf; fi += TPQ) {
            float abx = sf[0][fi],  aby = sf[1][fi],  abz = sf[2][fi];
            float acx = sf[3][fi],  acy = sf[4][fi],  acz = sf[5][fi];
            float ax  = sf[6][fi],  ay  = sf[7][fi],  az  = sf[8][fi];
            float ab_a= sf[9][fi],  ab_b= sf[10][fi], ab_c= sf[11][fi];
            float ac_a= sf[12][fi], ac_b= sf[13][fi], ac_c= sf[14][fi];
            float aa  = sf[15][fi], ab2 = sf[16][fi], ac2 = sf[17][fi];
            float abac= sf[18][fi];
            int fg = f0 + fi;
#pragma unroll
            for (int q = 0; q < NQ; q++) {
                // einsum('bfd,bsd->bsf'): asc-k FMA chain (gemm)
                float s  = dot3_fma(abx,aby,abz, px[q],py[q],pz[q]);
                float tt = dot3_fma(acx,acy,acz, px[q],py[q],pz[q]);
                float ap = dot3_fma(ax, ay, az,  px[q],py[q],pz[q]);
                float d1 = __fsub_rn(s,  ab_a), d2 = __fsub_rn(tt, ac_a);
                float v, w;
                region_vw(s, tt, ab_a, ab_b, ab_c, ac_a, ac_b, ac_c, v, w);
                // papa = (pp - 2*ap) + aa
                float papa = __fadd_rn(__fsub_rn(pp[q], __fmul_rn(2.0f, ap)), aa);
                // dist2 = ((((papa - 2v*d1) - 2w*d2) + v*v*ab2) + 2v*w*abac) + w*w*ac2
                float t1 = __fmul_rn(__fmul_rn(2.0f, v), d1);
                float e  = __fsub_rn(papa, t1);
                float t2 = __fmul_rn(__fmul_rn(2.0f, w), d2);
                e = __fsub_rn(e, t2);
                float t3 = __fmul_rn(__fmul_rn(v, v), ab2);
                e = __fadd_rn(e, t3);
                float t4 = __fmul_rn(__fmul_rn(__fmul_rn(2.0f, v), w), abac);
                e = __fadd_rn(e, t4);
                float t5 = __fmul_rn(__fmul_rn(w, w), ac2);
                float dist2 = __fadd_rn(e, t5);
                dist2 = fmaxf(dist2, 0.0f);
                if (dist2 < bd2[q]) { bd2[q] = dist2; bf[q] = fg; }
            }
        }
        __syncthreads();
    }

#pragma unroll
    for (int q = 0; q < NQ; q++) {
        int idx = tid * NQ + q;
        r_d2[idx] = bd2[q]; r_f[idx] = bf[q];
    }
    __syncthreads();

    if (tid < QB) {
        int qs = tid >> 2, ql = tid & 3;
        float bd = CUDART_INF_F; int fb = 0x7fffffff;
        for (int t2 = 0; t2 < TPQ; t2++) {
            int idx = (qs * TPQ + t2) * NQ + ql;
            float d = r_d2[idx]; int ff = r_f[idx];
            if (d < bd || (d == bd && ff < fb)) { bd = d; fb = ff; }
        }
        int qg = qblk + tid;
        g_pd2[slice][qg] = bd;
        g_pf [slice][qg] = fb;
    }
}

__global__ void smpl_finalize_kernel(const float* __restrict__ coords,
                                     const float* __restrict__ can_V,
                                     const int*   __restrict__ smpl_F,
                                     float* __restrict__ out) {
    int qg = blockIdx.x * blockDim.x + threadIdx.x;
    if (qg >= NQTOT) return;
    int b = qg / S_CNT;
    const int rbase = b * F_CNT;

    float bd = CUDART_INF_F; int fb = 0x7fffffff;
    for (int s = 0; s < NS; s++) {
        float d = g_pd2[s][qg]; int ff = g_pf[s][qg];
        if (d < bd || (d == bd && ff < fb)) { bd = d; fb = ff; }
    }

    float qx = coords[qg*3+0], qy = coords[qg*3+1], qz = coords[qg*3+2];
    int ridx = rbase + fb;
    float abx = g_face[0][ridx], aby = g_face[1][ridx], abz = g_face[2][ridx];
    float acx = g_face[3][ridx], acy = g_face[4][ridx], acz = g_face[5][ridx];
    float ax  = g_face[6][ridx], ay  = g_face[7][ridx], az  = g_face[8][ridx];

    // Recompute winner's (v,w) with the bit-identical op sequence.
    float s  = dot3_fma(abx,aby,abz, qx,qy,qz);
    float tt = dot3_fma(acx,acy,acz, qx,qy,qz);
    float fv, fw;
    region_vw(s, tt, g_face[9][ridx], g_face[10][ridx], g_face[11][ridx],
              g_face[12][ridx], g_face[13][ridx], g_face[14][ridx], fv, fw);

    // hitpt = (a + v*ab) + w*ac
    float hx = __fadd_rn(__fadd_rn(ax, __fmul_rn(fv,abx)), __fmul_rn(fw,acx));
    float hy = __fadd_rn(__fadd_rn(ay, __fmul_rn(fv,aby)), __fmul_rn(fw,acy));
    float hz = __fadd_rn(__fadd_rn(az, __fmul_rn(fv,abz)), __fmul_rn(fw,acz));
    float dx = __fsub_rn(hx, qx), dy = __fsub_rn(hy, qy), dz = __fsub_rn(hz, qz);
    // jnp.linalg.norm: sum-of-squares reduce -> tree
    float nrm = __fsqrt_rn(dot3_tree(dx,dy,dz, dx,dy,dz));
    float dn  = fmaxf(nrm, 1e-6f);
    float w0  = __fsub_rn(__fsub_rn(1.0f, fv), fw);
    int i0 = smpl_F[fb*3+0], i1 = smpl_F[fb*3+1], i2 = smpl_F[fb*3+2];
    // out_coord: reduce over verts axis (non-minor) -> sequential ascending
    float o0 = __fadd_rn(__fadd_rn(__fmul_rn(can_V[i0*3+0], w0),
                                   __fmul_rn(can_V[i1*3+0], fv)),
                         __fmul_rn(can_V[i2*3+0], fw));
    float o1 = __fadd_rn(__fadd_rn(__fmul_rn(can_V[i0*3+1], w0),
                                   __fmul_rn(can_V[i1*3+1], fv)),
                         __fmul_rn(can_V[i2*3+1], fw));
    float o2 = __fadd_rn(__fadd_rn(__fmul_rn(can_V[i0*3+2], w0),
                                   __fmul_rn(can_V[i1*3+2], fv)),
                         __fmul_rn(can_V[i2*3+2], fw));
    // output layout: out_coord (B,S,3) | sdf (B,S) | normal (B,S,3) | z (B,S,1)
    out[qg*3+0] = o0; out[qg*3+1] = o1; out[qg*3+2] = o2;
    out[NQTOT*3 + qg] = __fsqrt_rn(bd);
    out[NQTOT*4 + qg*3+0] = __fdiv_rn(dx, dn);
    out[NQTOT*4 + qg*3+1] = __fdiv_rn(dy, dn);
    out[NQTOT*4 + qg*3+2] = __fdiv_rn(dz, dn);
    out[NQTOT*7 + qg] = qz;
}

extern "C" void kernel_launch(void* const* d_in, const int* in_sizes, int n_in,
                              void* d_out, int out_size) {
    const float* coords = (const float*)d_in[0];
    const float* smpl_V = (const float*)d_in[1];
    const float* can_V  = (const float*)d_in[2];
    const int*   smpl_F = (const int*)d_in[3];
    float* out = (float*)d_out;

    face_precompute_kernel<<<(B_CNT * F_CNT + 255) / 256, 256>>>(smpl_V, smpl_F);
    smpl_scan_kernel<<<NS * NQBLK, NTHREADS>>>(coords);
    smpl_finalize_kernel<<<(NQTOT + 255) / 256, 256>>>(coords, can_V, smpl_F, out);
}